// round 15
// baseline (speedup 1.0000x reference)
#include <cuda_runtime.h>
#include <cuda_fp16.h>
#include <cstdint>

// Problem constants
#define Bsz 2
#define Tsz 2048
#define Csz 1024
#define Hn  16
#define Dh  64
#define GK  1024

typedef __half h16;

// ---------------------------------------------------------------------------
// Scratch (__device__ globals; no allocation allowed)
// ---------------------------------------------------------------------------
__device__ h16 g_xh[(size_t)4096 * 1024];
__device__ h16 g_wah[(size_t)3072 * 1024];
__device__ h16 g_wph[(size_t)1024 * 1024];
// Q,K: [b][h][t][d] ; V stored transposed: [b][h][d][t]
__device__ h16 g_qh[(size_t)32 * 2048 * 64];
__device__ h16 g_kh[(size_t)32 * 2048 * 64];
__device__ h16 g_vth[(size_t)32 * 2048 * 64];
// attention output (pre-projection): [b*T][C]
__device__ h16 g_y2h[(size_t)4096 * 1024];

// ---------------------------------------------------------------------------
// Base-ISA helpers (compile clean for compute_103 base target)
// ---------------------------------------------------------------------------
__device__ __forceinline__ uint32_t smem_u32(const void* p) {
    uint32_t a;
    asm("{ .reg .u64 t; cvta.to.shared.u64 t, %1; cvt.u32.u64 %0, t; }"
        : "=r"(a) : "l"(p));
    return a;
}
__device__ __forceinline__ void ldm4(uint32_t* r, uint32_t addr) {
    asm volatile("ldmatrix.sync.aligned.m8n8.x4.shared.b16 {%0,%1,%2,%3}, [%4];"
                 : "=r"(r[0]), "=r"(r[1]), "=r"(r[2]), "=r"(r[3]) : "r"(addr));
}
__device__ __forceinline__ void mma_f16(float* d, const uint32_t* a,
                                        uint32_t b0, uint32_t b1) {
    asm volatile(
        "mma.sync.aligned.m16n8k16.row.col.f32.f16.f16.f32 "
        "{%0,%1,%2,%3}, {%4,%5,%6,%7}, {%8,%9}, {%0,%1,%2,%3};"
        : "+f"(d[0]), "+f"(d[1]), "+f"(d[2]), "+f"(d[3])
        : "r"(a[0]), "r"(a[1]), "r"(a[2]), "r"(a[3]), "r"(b0), "r"(b1));
}
__device__ __forceinline__ void cp16(uint32_t dst, const void* src) {
    asm volatile("cp.async.cg.shared.global [%0], [%1], 16;"
                 :: "r"(dst), "l"(src) : "memory");
}
__device__ __forceinline__ void cp_commit() {
    asm volatile("cp.async.commit_group;" ::: "memory");
}
template<int N>
__device__ __forceinline__ void cp_wait() {
    asm volatile("cp.async.wait_group %0;" :: "n"(N) : "memory");
}
__device__ __forceinline__ uint32_t pack_f16(float x0, float x1) {
    __half2 v = __floats2half2_rn(x0, x1);
    return *reinterpret_cast<uint32_t*>(&v);
}

// ---------------------------------------------------------------------------
// One-shot fp32 -> fp16 convert of all three inputs (single launch)
// ---------------------------------------------------------------------------
#define NX2  (4096 * 1024 / 2)
#define NWA2 (3072 * 1024 / 2)
#define NWP2 (1024 * 1024 / 2)

__global__ void cvt_all(const float* __restrict__ x,
                        const float* __restrict__ wa,
                        const float* __restrict__ wp)
{
    int i = blockIdx.x * blockDim.x + threadIdx.x;
    if (i < NX2) {
        float2 v = ((const float2*)x)[i];
        ((uint32_t*)g_xh)[i] = pack_f16(v.x, v.y);
    } else if (i < NX2 + NWA2) {
        const int j = i - NX2;
        float2 v = ((const float2*)wa)[j];
        ((uint32_t*)g_wah)[j] = pack_f16(v.x, v.y);
    } else {
        const int j = i - NX2 - NWA2;
        float2 v = ((const float2*)wp)[j];
        ((uint32_t*)g_wph)[j] = pack_f16(v.x, v.y);
    }
}

// ===========================================================================
// Tensor-core GEMM (fp16 operands, fp32 accum), 3-stage cp.async pipeline,
// 128B swizzled smem rows, BK=64. C[m,n] = sum_k A[m,k]*W[n,k]; CTA 128x128.
// smem/CTA = 96KB -> 2 CTAs/SM.
// MODE 0: epilogue -> Q/K ([b][h][t][d], Q pre-scaled 1/8) + V^T ([b][h][d][t]).
// MODE 1: epilogue -> C fp32 [4096][1024].
// ===========================================================================
#define BK      64
#define NCH     (GK / BK)          // 16
#define TILE_B  (128 * 128)        // 16384: 128 rows x 128B (64 fp16), swizzled
#define BUF_B   (2 * TILE_B)       // 32768 (A, W)
#define STAGES  3
#define GEMM_SMEM (STAGES * BUF_B) // 98304

// Swizzled byte offset of 16B chunk (row r, chunk u in 0..7) within a tile.
__device__ __forceinline__ uint32_t swz(int r, int u) {
    return (uint32_t)(r * 128 + ((u ^ (r & 7)) * 16));
}

template<int MODE>
__global__ void __launch_bounds__(256, 2) gemm_tc(const h16* __restrict__ Ah,
                                                  const h16* __restrict__ Wh,
                                                  float* __restrict__ C)
{
    extern __shared__ char smc[];

    const int tid = threadIdx.x;
    const int wid = tid >> 5;
    const int l   = tid & 31;
    const int m0  = blockIdx.y * 128;
    const int n0  = blockIdx.x * 128;
    const int wm  = wid & 1;
    const int wn  = wid >> 1;

    // 8 cp.async slots/thread: f = tid + q*256; tile = f>>10 (A, W)
    const h16* src[8];
    uint32_t soff[8];
#pragma unroll
    for (int q = 0; q < 8; q++) {
        const int f = tid + q * 256;
        const int tile = f >> 10, g = f & 1023;
        const int r = g >> 3, u = g & 7;
        const int row = (tile == 0 ? m0 : n0) + r;
        src[q]  = (tile == 0 ? Ah : Wh) + (size_t)row * GK + u * 8;
        soff[q] = (uint32_t)(tile * TILE_B) + swz(r, u);
    }
    const uint32_t sb = smem_u32(smc);

    // Prologue: issue stages 0..1
#pragma unroll
    for (int s = 0; s < STAGES - 1; s++) {
        const uint32_t dst = sb + (uint32_t)s * BUF_B;
        const int k0 = s * BK;
#pragma unroll
        for (int q = 0; q < 8; q++) cp16(dst + soff[q], src[q] + k0);
        cp_commit();
    }

    float acc[4][4][4];
#pragma unroll
    for (int i = 0; i < 4; i++)
#pragma unroll
        for (int j = 0; j < 4; j++)
#pragma unroll
            for (int k = 0; k < 4; k++) acc[i][j][k] = 0.f;

    const int lrow = l & 15;
    const int lku  = l >> 4;

    for (int c = 0; c < NCH; c++) {
        cp_wait<STAGES - 2>();      // stage c landed
        __syncthreads();

        const uint32_t buf = sb + (uint32_t)(c % STAGES) * BUF_B;
#pragma unroll
        for (int s = 0; s < 4; s++) {           // 4 k16 steps per 64-chunk
            uint32_t ah[4][4], bh[2][4];
            const int ku = 2 * s + lku;          // 16B chunk index 0..7
#pragma unroll
            for (int i = 0; i < 4; i++) {
                const int row = wm * 64 + i * 16 + lrow;
                ldm4(ah[i], buf + swz(row, ku));
            }
#pragma unroll
            for (int jp = 0; jp < 2; jp++) {
                const int row = wn * 32 + jp * 16 + lrow;
                ldm4(bh[jp], buf + TILE_B + swz(row, ku));
            }
#pragma unroll
            for (int i = 0; i < 4; i++)
#pragma unroll
                for (int j = 0; j < 4; j++) {
                    const int jp = j >> 1, p = j & 1;
                    mma_f16(acc[i][j], ah[i], bh[jp][p], bh[jp][p + 2]);
                }
        }

        // Issue stage c+2 into buffer (c+2)%3 == (c-1)%3 (consumed at c-1)
        const int nc = c + STAGES - 1;
        if (nc < NCH) {
            const uint32_t dst = sb + (uint32_t)(nc % STAGES) * BUF_B;
            const int k0 = nc * BK;
#pragma unroll
            for (int q = 0; q < 8; q++) cp16(dst + soff[q], src[q] + k0);
        }
        cp_commit();
    }

    // Epilogue
#pragma unroll
    for (int i = 0; i < 4; i++) {
#pragma unroll
        for (int j = 0; j < 4; j++) {
            const int gm0 = m0 + wm * 64 + i * 16 + (l >> 2);
            const int gn  = n0 + wn * 32 + j * 8 + 2 * (l & 3);
#pragma unroll
            for (int half = 0; half < 2; half++) {
                const int gm = gm0 + half * 8;
                float vx = acc[i][j][half * 2], vy = acc[i][j][half * 2 + 1];
                if (MODE == 1) {
                    *(float2*)&C[(size_t)gm * Csz + gn] = make_float2(vx, vy);
                } else {
                    const int b = gm >> 11, t = gm & (Tsz - 1);
                    const int which = gn >> 10, cc = gn & (Csz - 1);
                    const int h = cc >> 6, d = cc & 63;
                    if (which == 0) { vx *= 0.125f; vy *= 0.125f; }  // 1/sqrt(D)
                    const uint32_t hh = pack_f16(vx, vy);
                    const size_t bh_ = (size_t)b * Hn + h;
                    if (which == 0) {
                        *(uint32_t*)&g_qh[(bh_ * Tsz + t) * Dh + d] = hh;
                    } else if (which == 1) {
                        *(uint32_t*)&g_kh[(bh_ * Tsz + t) * Dh + d] = hh;
                    } else {  // V transposed: [b][h][d][t]
                        const __half2 hv = *reinterpret_cast<const __half2*>(&hh);
                        g_vth[(bh_ * Dh + d)     * Tsz + t] = __low2half(hv);
                        g_vth[(bh_ * Dh + d + 1) * Tsz + t] = __high2half(hv);
                    }
                }
            }
        }
    }
}

// ===========================================================================
// Tensor-core causal flash attention (fp16), cp.async double-buffered K/V.
// CTA = 128 queries of one (b,h); 256 threads / 8 warps (warp = 16 q rows).
// 64-key tiles; each loaded K/V tile now feeds 128 queries (2x amortization).
// S = Q K^T, online softmax in frags, P repacked from S frags, O += P V
// vs smem V^T. Output fp16 into g_y2h. smem 54KB, ~2 CTAs/SM by regs.
// ===========================================================================
#define ARS    144                 // 64 fp16 = 128B + 16B pad
#define AQ_B   (128 * ARS)         // 18432 (Q tile, 128 rows)
#define AT_B   (64 * ARS)          // 9216  (K or V tile, 64 rows)
#define ASTG0  (AQ_B)              // stage base
#define ASTG_B (2 * AT_B)          // K, V per stage = 18432
#define AK_H   0
#define AV_H   (AT_B)
#define ATTN_SMEM (ASTG0 + 2 * ASTG_B)   // 55296

__global__ void __launch_bounds__(256) attn_tc()
{
    extern __shared__ char sma[];
    const uint32_t sb = smem_u32(sma);

    const int qt  = (int)gridDim.x - 1 - (int)blockIdx.x;  // heavy tiles first
    const int h   = blockIdx.y;
    const int b   = blockIdx.z;
    const int tid = threadIdx.x;
    const int w   = tid >> 5;          // 0..7, rows 16w..16w+15
    const int l   = tid & 31;
    const int lrow = l & 15;
    const int lku  = l >> 4;
    const int q0   = qt * 128;
    const int njt  = 2 * (qt + 1);     // number of 64-key tiles

    const size_t bh_  = (size_t)b * Hn + h;
    const h16* qhG  = g_qh  + (bh_ * Tsz + q0) * Dh;
    const h16* khG  = g_kh  + bh_ * Tsz * Dh;
    const h16* vthG = g_vth + bh_ * Dh * Tsz;

    // Issue K/V tile jt into stage st (1024 cp16 slots over 256 threads)
    auto issue_tile = [&](int jt, int st) {
        const int kk0 = jt * 64;
        const uint32_t base = sb + ASTG0 + (uint32_t)st * ASTG_B;
#pragma unroll
        for (int q = 0; q < 4; q++) {
            const int idx = tid + q * 256;
            const int arr = idx >> 9, g = idx & 511;
            const int r = g >> 3, u = g & 7;
            const uint32_t dst = base + (uint32_t)(arr * AT_B + r * ARS + u * 16);
            const h16* s = (arr == 0) ? (khG + (size_t)(kk0 + r) * Dh + u * 8)
                                      : (vthG + (size_t)r * Tsz + kk0 + u * 8);
            cp16(dst, s);
        }
        cp_commit();
    };

    issue_tile(0, 0);

    // Q tile (128 rows) -> smem -> register fragments
#pragma unroll
    for (int q = 0; q < 4; q++) {
        const int idx = tid + q * 256;
        const int r = idx >> 3, u = idx & 7;
        *(uint4*)(sma + r * ARS + u * 16) = *(const uint4*)(qhG + r * Dh + u * 8);
    }
    __syncthreads();

    uint32_t qh[4][4];
#pragma unroll
    for (int ks = 0; ks < 4; ks++) {
        const uint32_t addr = sb + (uint32_t)((16 * w + lrow) * ARS + ks * 32 + lku * 16);
        ldm4(qh[ks], addr);
    }

    float m0v = -1e30f, m1v = -1e30f, l0v = 0.f, l1v = 0.f;
    float o[8][4];
#pragma unroll
    for (int j = 0; j < 8; j++)
#pragma unroll
        for (int k = 0; k < 4; k++) o[j][k] = 0.f;

    for (int jt = 0; jt < njt; jt++) {
        // Prefetch next tile (into the stage holding jt-1, already consumed)
        if (jt + 1 < njt) { issue_tile(jt + 1, (jt + 1) & 1); cp_wait<1>(); }
        else              { cp_wait<0>(); }
        __syncthreads();

        const uint32_t stg = sb + ASTG0 + (uint32_t)(jt & 1) * ASTG_B;

        // ---- S = Q K^T ----
        float s[8][4];
#pragma unroll
        for (int j = 0; j < 8; j++)
#pragma unroll
            for (int k = 0; k < 4; k++) s[j][k] = 0.f;

#pragma unroll
        for (int ks = 0; ks < 4; ks++) {
            uint32_t kh[4][4];
            const uint32_t kc = (uint32_t)(ks * 32 + lku * 16);
#pragma unroll
            for (int jp = 0; jp < 4; jp++) {
                ldm4(kh[jp], stg + AK_H + (uint32_t)((16 * jp + lrow) * ARS) + kc);
            }
#pragma unroll
            for (int j = 0; j < 8; j++) {
                const int jp = j >> 1, p = j & 1;
                mma_f16(s[j], qh[ks], kh[jp][p], kh[jp][p + 2]);
            }
        }

        // ---- Causal mask (the two diagonal tiles only: keys reach queries) ----
        if (jt >= 2 * qt) {
            const int row0 = q0 + 16 * w + (l >> 2);   // global query row
            const int c0   = jt * 64;                  // global key base
#pragma unroll
            for (int j = 0; j < 8; j++) {
                const int col = c0 + j * 8 + 2 * (l & 3);
                if (col     > row0)     s[j][0] = -1e30f;
                if (col + 1 > row0)     s[j][1] = -1e30f;
                if (col     > row0 + 8) s[j][2] = -1e30f;
                if (col + 1 > row0 + 8) s[j][3] = -1e30f;
            }
        }

        // ---- Online softmax (row = 4 consecutive lanes) ----
        float mx0 = -1e30f, mx1 = -1e30f;
#pragma unroll
        for (int j = 0; j < 8; j++) {
            mx0 = fmaxf(mx0, fmaxf(s[j][0], s[j][1]));
            mx1 = fmaxf(mx1, fmaxf(s[j][2], s[j][3]));
        }
        mx0 = fmaxf(mx0, __shfl_xor_sync(0xffffffffu, mx0, 1));
        mx0 = fmaxf(mx0, __shfl_xor_sync(0xffffffffu, mx0, 2));
        mx1 = fmaxf(mx1, __shfl_xor_sync(0xffffffffu, mx1, 1));
        mx1 = fmaxf(mx1, __shfl_xor_sync(0xffffffffu, mx1, 2));

        const float nm0 = fmaxf(m0v, mx0), nm1 = fmaxf(m1v, mx1);
        const float a0 = __expf(m0v - nm0), a1 = __expf(m1v - nm1);
        float rs0 = 0.f, rs1 = 0.f;
#pragma unroll
        for (int j = 0; j < 8; j++) {
            s[j][0] = __expf(s[j][0] - nm0); rs0 += s[j][0];
            s[j][1] = __expf(s[j][1] - nm0); rs0 += s[j][1];
            s[j][2] = __expf(s[j][2] - nm1); rs1 += s[j][2];
            s[j][3] = __expf(s[j][3] - nm1); rs1 += s[j][3];
        }
        rs0 += __shfl_xor_sync(0xffffffffu, rs0, 1);
        rs0 += __shfl_xor_sync(0xffffffffu, rs0, 2);
        rs1 += __shfl_xor_sync(0xffffffffu, rs1, 1);
        rs1 += __shfl_xor_sync(0xffffffffu, rs1, 2);
        l0v = l0v * a0 + rs0; m0v = nm0;
        l1v = l1v * a1 + rs1; m1v = nm1;
#pragma unroll
        for (int j = 0; j < 8; j++) {
            o[j][0] *= a0; o[j][1] *= a0;
            o[j][2] *= a1; o[j][3] *= a1;
        }

        // ---- P frags from S frags; O += P V ----
#pragma unroll
        for (int kt = 0; kt < 4; kt++) {
            uint32_t ph[4];
            ph[0] = pack_f16(s[2 * kt][0],     s[2 * kt][1]);
            ph[1] = pack_f16(s[2 * kt][2],     s[2 * kt][3]);
            ph[2] = pack_f16(s[2 * kt + 1][0], s[2 * kt + 1][1]);
            ph[3] = pack_f16(s[2 * kt + 1][2], s[2 * kt + 1][3]);

            uint32_t vh[4][4];
            const uint32_t kc = (uint32_t)(kt * 32 + lku * 16);
#pragma unroll
            for (int dp = 0; dp < 4; dp++) {
                ldm4(vh[dp], stg + AV_H + (uint32_t)((16 * dp + lrow) * ARS) + kc);
            }
#pragma unroll
            for (int jd = 0; jd < 8; jd++) {
                const int dp = jd >> 1, p = jd & 1;
                mma_f16(o[jd], ph, vh[dp][p], vh[dp][p + 2]);
            }
        }
        __syncthreads();   // all reads of this stage done before overwrite
    }

    // ---- Normalize + write y2 as fp16 ----
    const float inv0 = 1.f / l0v, inv1 = 1.f / l1v;
    const int r0g = q0 + 16 * w + (l >> 2);
#pragma unroll
    for (int jd = 0; jd < 8; jd++) {
        const int col = h * Dh + jd * 8 + 2 * (l & 3);
        *(uint32_t*)&g_y2h[((size_t)b * Tsz + r0g) * Csz + col] =
            pack_f16(o[jd][0] * inv0, o[jd][1] * inv0);
        *(uint32_t*)&g_y2h[((size_t)b * Tsz + r0g + 8) * Csz + col] =
            pack_f16(o[jd][2] * inv1, o[jd][3] * inv1);
    }
}

// ===========================================================================
extern "C" void kernel_launch(void* const* d_in, const int* in_sizes, int n_in,
                              void* d_out, int out_size)
{
    const float* x      = (const float*)d_in[0];   // [B,T,C]
    const float* w_attn = (const float*)d_in[1];   // [3C,C]
    const float* w_proj = (const float*)d_in[2];   // [C,C]
    float* out = (float*)d_out;                    // [B,T,C]

    cudaFuncSetAttribute(gemm_tc<0>, cudaFuncAttributeMaxDynamicSharedMemorySize, GEMM_SMEM);
    cudaFuncSetAttribute(gemm_tc<1>, cudaFuncAttributeMaxDynamicSharedMemorySize, GEMM_SMEM);
    cudaFuncSetAttribute(attn_tc,    cudaFuncAttributeMaxDynamicSharedMemorySize, ATTN_SMEM);

    h16 *xh, *wah, *wph, *y2h;
    cudaGetSymbolAddress((void**)&xh,  g_xh);
    cudaGetSymbolAddress((void**)&wah, g_wah);
    cudaGetSymbolAddress((void**)&wph, g_wph);
    cudaGetSymbolAddress((void**)&y2h, g_y2h);

    // 0) One-shot fp32 -> fp16 converts (single launch)
    {
        const int total = NX2 + NWA2 + NWP2;
        cvt_all<<<(total + 255) / 256, 256>>>(x, w_attn, w_proj);
    }

    // 1) QKV projection -> Q/K ([b][h][t][d]) + V^T ([b][h][d][t]) fp16
    {
        dim3 grid((3 * Csz) / 128, (Bsz * Tsz) / 128);   // (24, 32)
        gemm_tc<0><<<grid, 256, GEMM_SMEM>>>(xh, wah, nullptr);
    }

    // 2) Tensor-core causal flash attention -> g_y2 (fp16)
    {
        dim3 grid(Tsz / 128, Hn, Bsz);                   // (16, 16, 2)
        attn_tc<<<grid, 256, ATTN_SMEM>>>();
    }

    // 3) Output projection -> d_out (fp32)
    {
        dim3 grid(Csz / 128, (Bsz * Tsz) / 128);         // (8, 32)
        gemm_tc<1><<<grid, 256, GEMM_SMEM>>>(y2h, wph, out);
    }
}